// round 4
// baseline (speedup 1.0000x reference)
#include <cuda_runtime.h>
#include <math.h>

#define BB 4
#define C 128
#define H 256
#define W 256
#define HW (H*W)

// ---------------- scratch (device globals; no allocations allowed) ----------------
__device__ float g_h[(size_t)BB*C*HW];     // 128 MB
__device__ float g_v[(size_t)BB*C*HW];     // 128 MB
__device__ float g_hsum[BB*C];
__device__ float g_vsum[BB*C];
__device__ float g_gate[BB*2];

// ---------------- K0: zero pooling accumulators (graph-replay safe) ----------------
__global__ void k0_zero() {
    int t = threadIdx.x;
    if (t < BB*C) { g_hsum[t] = 0.f; g_vsum[t] = 0.f; }
}

// ---------------- K1h: exact two-stage horizontal conv, 4 rows/block ---------------
// stage1: s1[q] = sum_i h1[i]*x_pad[q+i-2]  (q in [0,W), zero outside)
// stage2: h[p]  = sum_j h2[j]*s1_pad[p+3j-9]
__global__ void __launch_bounds__(256) k1_h(const float* __restrict__ x,
                                            const float* __restrict__ h1w,
                                            const float* __restrict__ h2w) {
    int blk = blockIdx.x;                  // BB*C*(H/4)
    int rowblk = blk % (H/4);
    int bc = blk / (H/4);
    int c = bc % C;
    const float* xp = x + (size_t)bc*HW + (size_t)rowblk*4*W;
    float* hp = g_h + (size_t)bc*HW + (size_t)rowblk*4*W;

    __shared__ float smx[4][W + 4];        // x with 2-halo (zero padded)
    __shared__ float sm1[4][W + 18];       // stage1 with 9-zero halo each side
    int t = threadIdx.x;

    float w1[5], w2[7];
    #pragma unroll
    for (int i = 0; i < 5; i++) w1[i] = h1w[c*5 + i];
    #pragma unroll
    for (int j = 0; j < 7; j++) w2[j] = h2w[c*7 + j];

    for (int idx = t; idx < 4*(W + 4); idx += 256) {
        int r = idx / (W + 4), sc = idx % (W + 4);
        int col = sc - 2;
        smx[r][sc] = (col >= 0 && col < W) ? xp[r*W + col] : 0.f;
    }
    for (int idx = t; idx < 4*(W + 18); idx += 256) {
        int r = idx / (W + 18), sc = idx % (W + 18);
        sm1[r][sc] = 0.f;
    }
    __syncthreads();
    for (int idx = t; idx < 4*W; idx += 256) {
        int r = idx >> 8, q = idx & 255;
        float s = 0.f;
        #pragma unroll
        for (int i = 0; i < 5; i++) s = fmaf(w1[i], smx[r][q + i], s);
        sm1[r][9 + q] = s;
    }
    __syncthreads();

    int r = t >> 6, lane = t & 63;
    int p0 = lane * 4;
    // h[p] = sum_j w2[j] * sm1[r][p + 3j]   (index 9 + p + 3j - 9)
    float win[22];
    #pragma unroll
    for (int i = 0; i < 22; i++) win[i] = sm1[r][p0 + i];
    float a0 = 0.f, a1 = 0.f, a2 = 0.f, a3 = 0.f;
    #pragma unroll
    for (int j = 0; j < 7; j++) {
        float e = w2[j];
        a0 = fmaf(e, win[3*j],     a0);
        a1 = fmaf(e, win[3*j + 1], a1);
        a2 = fmaf(e, win[3*j + 2], a2);
        a3 = fmaf(e, win[3*j + 3], a3);
    }
    *(float4*)(hp + r*W + p0) = make_float4(a0, a1, a2, a3);

    float s = a0 + a1 + a2 + a3;
    #pragma unroll
    for (int off = 16; off; off >>= 1) s += __shfl_down_sync(0xffffffffu, s, off);
    __shared__ float ssum[8];
    if ((t & 31) == 0) ssum[t >> 5] = s;
    __syncthreads();
    if (t == 0) {
        float tot = 0.f;
        #pragma unroll
        for (int i = 0; i < 8; i++) tot += ssum[i];
        atomicAdd(&g_hsum[bc], tot);
    }
}

// ---------------- K1v: exact two-stage vertical conv, 64x32 tile -------------------
__global__ void __launch_bounds__(256) k1_v(const float* __restrict__ x,
                                            const float* __restrict__ v1w,
                                            const float* __restrict__ v2w) {
    int blk = blockIdx.x;                  // BB*C*(H/64)*(W/32)
    int xt = blk % (W/32); blk /= (W/32);
    int yt = blk % (H/64); blk /= (H/64);
    int bc = blk;
    int c = bc % C;
    const float* xp = x + (size_t)bc*HW;
    float* vp = g_v + (size_t)bc*HW;
    int x0 = xt*32, y0 = yt*64;

    __shared__ float smx[86][32];          // x rows y0-11 .. y0+74 (zero padded)
    __shared__ float sm1[82][32];          // stage1 rows y0-9 .. y0+72 (zeroed OOB)
    int t = threadIdx.x;

    float w1[5], w2[7];
    #pragma unroll
    for (int i = 0; i < 5; i++) w1[i] = v1w[c*5 + i];
    #pragma unroll
    for (int j = 0; j < 7; j++) w2[j] = v2w[c*7 + j];

    for (int idx = t; idx < 86*32; idx += 256) {
        int r = idx >> 5, col = idx & 31;
        int gy = y0 + r - 11;
        smx[r][col] = (gy >= 0 && gy < H) ? xp[gy*W + x0 + col] : 0.f;
    }
    __syncthreads();
    // s1 at global row g = y0-9+r1:  sum_i w1[i]*x[g+i-2]  -> smx[r1+i]
    for (int idx = t; idx < 82*32; idx += 256) {
        int r1 = idx >> 5, col = idx & 31;
        int g = y0 - 9 + r1;
        float s = 0.f;
        if (g >= 0 && g < H) {
            #pragma unroll
            for (int i = 0; i < 5; i++) s = fmaf(w1[i], smx[r1 + i][col], s);
        }
        sm1[r1][col] = s;
    }
    __syncthreads();

    int tx = t & 31, ty = t >> 5;          // ty 0..7
    int yb = ty * 8;
    // v at global row y0+yb+ii = sum_j w2[j]*s1[row yb+ii+3j]
    float win[26];
    #pragma unroll
    for (int i = 0; i < 26; i++) win[i] = sm1[yb + i][tx];
    float acc[8];
    #pragma unroll
    for (int i = 0; i < 8; i++) acc[i] = 0.f;
    #pragma unroll
    for (int j = 0; j < 7; j++) {
        float e = w2[j];
        #pragma unroll
        for (int i = 0; i < 8; i++) acc[i] = fmaf(e, win[i + 3*j], acc[i]);
    }
    float s = 0.f;
    #pragma unroll
    for (int i = 0; i < 8; i++) {
        vp[(size_t)(y0 + yb + i)*W + x0 + tx] = acc[i];
        s += acc[i];
    }
    #pragma unroll
    for (int off = 16; off; off >>= 1) s += __shfl_down_sync(0xffffffffu, s, off);
    __shared__ float ssum[8];
    if ((t & 31) == 0) ssum[t >> 5] = s;
    __syncthreads();
    if (t == 0) {
        float tot = 0.f;
        #pragma unroll
        for (int i = 0; i < 8; i++) tot += ssum[i];
        atomicAdd(&g_vsum[bc], tot);
    }
}

// ---------------- K2: gate MLP + softmax (tiny) -------------------------------------
__global__ void k2_gate(const float* __restrict__ g1, const float* __restrict__ g2,
                        const float* __restrict__ g2b) {
    __shared__ float sg[BB][32];
    __shared__ float sl[BB][2];
    int t = threadIdx.x;                   // 128
    if (t < BB*32) {
        int b = t >> 5, k = t & 31;
        const float inv = 1.f / 65536.f;
        float acc = 0.f;
        for (int c2 = 0; c2 < C; c2++)
            acc = fmaf(g_hsum[b*C + c2] * inv, g1[k*(2*C) + c2], acc);
        for (int c2 = 0; c2 < C; c2++)
            acc = fmaf(g_vsum[b*C + c2] * inv, g1[k*(2*C) + C + c2], acc);
        float sig = 1.f / (1.f + expf(-acc));
        sg[b][k] = acc * sig;              // SiLU
    }
    __syncthreads();
    if (t < BB*2) {
        int b = t >> 1, j = t & 1;
        float acc = g2b[j];
        for (int k = 0; k < 32; k++) acc = fmaf(sg[b][k], g2[j*32 + k], acc);
        sl[b][j] = acc;
    }
    __syncthreads();
    if (t < BB) {
        float a = sl[t][0], b2 = sl[t][1];
        float m = fmaxf(a, b2);
        float e0 = expf(a - m), e1 = expf(b2 - m);
        float inv = 1.f / (e0 + e1);
        g_gate[t*2 + 0] = e0 * inv;
        g_gate[t*2 + 1] = e1 * inv;
    }
}

// ---------------- K3: fused gate-blend + 1x1 conv GEMM + residual -------------------
// out[b,o,p] = x * (0.5 + 0.5*(sum_c fw[o,c]*(wh*h + wv*v) + fb[o]))
__global__ void __launch_bounds__(256) k3_fuse(const float* __restrict__ x,
                                               const float* __restrict__ fw,
                                               const float* __restrict__ fb,
                                               float* __restrict__ out) {
    int blk = blockIdx.x;                  // BB * (HW/128)
    int pt = blk % (HW/128);
    int b  = blk / (HW/128);
    int p0 = pt * 128;

    __shared__ float sW[32][128];          // [c_local][o]
    __shared__ float sA[32][128];          // [c_local][p]
    int t = threadIdx.x;
    int tp = t & 15, to = t >> 4;
    float wh = g_gate[b*2 + 0], wv = g_gate[b*2 + 1];

    float acc[8][8];
    #pragma unroll
    for (int j = 0; j < 8; j++)
        #pragma unroll
        for (int i = 0; i < 8; i++) acc[j][i] = 0.f;

    for (int kk = 0; kk < C; kk += 32) {
        __syncthreads();
        for (int idx = t; idx < 32*128; idx += 256) {
            int o = idx >> 5, cl = idx & 31;
            sW[cl][o] = fw[o*C + kk + cl];
        }
        for (int idx = t; idx < 32*128; idx += 256) {
            int cl = idx >> 7, p = idx & 127;
            size_t gi = ((size_t)(b*C + kk + cl))*HW + p0 + p;
            sA[cl][p] = fmaf(wh, g_h[gi], wv * g_v[gi]);
        }
        __syncthreads();
        #pragma unroll
        for (int cl = 0; cl < 32; cl++) {
            float af[8], wf[8];
            #pragma unroll
            for (int i = 0; i < 8; i++) af[i] = sA[cl][tp + 16*i];
            #pragma unroll
            for (int j = 0; j < 8; j++) wf[j] = sW[cl][to + 16*j];
            #pragma unroll
            for (int j = 0; j < 8; j++)
                #pragma unroll
                for (int i = 0; i < 8; i++)
                    acc[j][i] = fmaf(wf[j], af[i], acc[j][i]);
        }
    }

    #pragma unroll
    for (int j = 0; j < 8; j++) {
        int o = to + 16*j;
        float bo = fb[o];
        size_t rowbase = ((size_t)(b*C + o))*HW + p0;
        #pragma unroll
        for (int i = 0; i < 8; i++) {
            int pl = tp + 16*i;
            float xv = x[rowbase + pl];
            out[rowbase + pl] = xv * (0.5f + 0.5f*(acc[j][i] + bo));
        }
    }
}

// ---------------- launch -------------------------------------------------------------
extern "C" void kernel_launch(void* const* d_in, const int* in_sizes, int n_in,
                              void* d_out, int out_size) {
    const float* x   = (const float*)d_in[0];
    const float* h1  = (const float*)d_in[1];
    const float* h2  = (const float*)d_in[2];
    const float* v1  = (const float*)d_in[3];
    const float* v2  = (const float*)d_in[4];
    const float* g1  = (const float*)d_in[5];
    const float* g2  = (const float*)d_in[6];
    const float* g2b = (const float*)d_in[7];
    const float* fw  = (const float*)d_in[8];
    const float* fb  = (const float*)d_in[9];
    float* out = (float*)d_out;

    k0_zero<<<1, 512>>>();
    k1_h<<<BB*C*(H/4), 256>>>(x, h1, h2);
    k1_v<<<BB*C*(H/64)*(W/32), 256>>>(x, v1, v2);
    k2_gate<<<1, 128>>>(g1, g2, g2b);
    k3_fuse<<<BB*(HW/128), 256>>>(x, fw, fb, out);
}

// round 5
// speedup vs baseline: 1.2258x; 1.2258x over previous
#include <cuda_runtime.h>
#include <math.h>

#define BB 4
#define C 128
#define H 256
#define W 256
#define HW (H*W)

#define GRID_H (BB*C*(H/8))            // 16384: 1 warp = 1 row, 8 rows/block
#define GRID_V (BB*C*(H/64)*(W/32))    // 16384: 64x32 tile, 8 rows/thread

// ---------------- scratch (device globals; no allocations allowed) ----------------
__device__ float g_h[(size_t)BB*C*HW];     // 128 MB
__device__ float g_v[(size_t)BB*C*HW];     // 128 MB
__device__ float g_hpart[BB*C*32];         // per-block partial sums (all rewritten each run)
__device__ float g_vpart[BB*C*32];
__device__ float g_gate[BB*2];

// ---------------- K1: both directional two-stage convs, register-only --------------
// stage1 (5-tap, pad 2) -> zero-padded intermediate -> stage2 (7-tap, dil 3, pad 9)
__global__ void __launch_bounds__(256) k1_conv(const float* __restrict__ x,
                                               const float* __restrict__ h1w,
                                               const float* __restrict__ h2w,
                                               const float* __restrict__ v1w,
                                               const float* __restrict__ v2w) {
    int blk = blockIdx.x;
    int t = threadIdx.x;
    __shared__ float ssum[8];

    float acc[8];
    float thread_sum;
    int bc, partIdx;

    if (blk < GRID_H) {
        // -------- horizontal --------
        int rowblk = blk & 31;
        bc = blk >> 5;
        int c = bc & (C - 1);
        int r = t >> 5, lane = t & 31;
        int p0 = lane * 8;
        int row = rowblk * 8 + r;
        const float* xr = x + (size_t)bc*HW + (size_t)row*W;

        float w1[5], w2[7];
        #pragma unroll
        for (int i = 0; i < 5; i++) w1[i] = h1w[c*5 + i];
        #pragma unroll
        for (int j = 0; j < 7; j++) w2[j] = h2w[c*7 + j];

        float win[30];                 // x[p0-11 .. p0+18], zero padded
        #pragma unroll
        for (int m = 0; m < 30; m++) {
            int q = p0 - 11 + m;
            win[m] = (q >= 0 && q < W) ? xr[q] : 0.f;
        }
        float s1[26];                  // stage1 at q = p0-9+k, zero outside [0,W)
        #pragma unroll
        for (int k = 0; k < 26; k++) {
            int q = p0 - 9 + k;
            float s = 0.f;
            if (q >= 0 && q < W) {
                #pragma unroll
                for (int i = 0; i < 5; i++) s = fmaf(w1[i], win[k + i], s);
            }
            s1[k] = s;
        }
        #pragma unroll
        for (int d = 0; d < 8; d++) {
            float a = 0.f;
            #pragma unroll
            for (int j = 0; j < 7; j++) a = fmaf(w2[j], s1[d + 3*j], a);
            acc[d] = a;
        }
        float* hp = g_h + (size_t)bc*HW + (size_t)row*W + p0;
        *(float4*)(hp)     = make_float4(acc[0], acc[1], acc[2], acc[3]);
        *(float4*)(hp + 4) = make_float4(acc[4], acc[5], acc[6], acc[7]);
        partIdx = bc*32 + rowblk;
        thread_sum = 0.f;
        #pragma unroll
        for (int d = 0; d < 8; d++) thread_sum += acc[d];
    } else {
        // -------- vertical --------
        int blk2 = blk - GRID_H;
        int xt = blk2 & 7;
        int yt = (blk2 >> 3) & 3;
        bc = blk2 >> 5;
        int c = bc & (C - 1);
        int tx = t & 31, ty = t >> 5;
        int col = xt*32 + tx;
        int y0 = yt*64 + ty*8;
        const float* xc = x + (size_t)bc*HW + col;

        float w1[5], w2[7];
        #pragma unroll
        for (int i = 0; i < 5; i++) w1[i] = v1w[c*5 + i];
        #pragma unroll
        for (int j = 0; j < 7; j++) w2[j] = v2w[c*7 + j];

        float win[30];                 // x rows y0-11 .. y0+18 at this column
        #pragma unroll
        for (int m = 0; m < 30; m++) {
            int gy = y0 - 11 + m;
            win[m] = (gy >= 0 && gy < H) ? xc[gy*W] : 0.f;
        }
        float s1[26];
        #pragma unroll
        for (int k = 0; k < 26; k++) {
            int gy = y0 - 9 + k;
            float s = 0.f;
            if (gy >= 0 && gy < H) {
                #pragma unroll
                for (int i = 0; i < 5; i++) s = fmaf(w1[i], win[k + i], s);
            }
            s1[k] = s;
        }
        float* vpb = g_v + (size_t)bc*HW + col;
        thread_sum = 0.f;
        #pragma unroll
        for (int d = 0; d < 8; d++) {
            float a = 0.f;
            #pragma unroll
            for (int j = 0; j < 7; j++) a = fmaf(w2[j], s1[d + 3*j], a);
            vpb[(y0 + d)*W] = a;       // coalesced across warp
            thread_sum += a;
        }
        partIdx = bc*32 + (yt*8 + xt);
    }

    // block reduction of thread_sum -> one partial per block (no atomics, no zeroing)
    float s = thread_sum;
    #pragma unroll
    for (int off = 16; off; off >>= 1) s += __shfl_down_sync(0xffffffffu, s, off);
    if ((t & 31) == 0) ssum[t >> 5] = s;
    __syncthreads();
    if (t == 0) {
        float tot = 0.f;
        #pragma unroll
        for (int i = 0; i < 8; i++) tot += ssum[i];
        if (blockIdx.x < GRID_H) g_hpart[partIdx] = tot;
        else                     g_vpart[partIdx] = tot;
    }
}

// ---------------- K2: gate MLP + softmax, 512 threads --------------------------------
__global__ void __launch_bounds__(512) k2_gate(const float* __restrict__ g1,
                                               const float* __restrict__ g2,
                                               const float* __restrict__ g2b) {
    __shared__ float shs[BB*C];
    __shared__ float svs[BB*C];
    __shared__ float sp[BB][32][4];
    __shared__ float sg[BB][32];
    __shared__ float sl[BB][2];
    int t = threadIdx.x;

    // phase 1: reduce 32 partials per (b,c)
    {
        int bc = t;                    // 512 == BB*C
        float s = 0.f;
        #pragma unroll 8
        for (int i = 0; i < 32; i++) s += g_hpart[bc*32 + i];
        shs[bc] = s;
        s = 0.f;
        #pragma unroll 8
        for (int i = 0; i < 32; i++) s += g_vpart[bc*32 + i];
        svs[bc] = s;
    }
    __syncthreads();

    // phase 2: MLP layer 1 (pooled[256] @ g1^T[256,32]) chunked 4-way
    {
        int b = t >> 7, k = (t >> 2) & 31, c4 = t & 3;
        const float inv = 1.f / 65536.f;
        float acc = 0.f;
        int cc0 = c4 * 64;
        #pragma unroll 8
        for (int cc = cc0; cc < cc0 + 64; cc++) {
            float p = (cc < C ? shs[b*C + cc] : svs[b*C + cc - C]) * inv;
            acc = fmaf(p, g1[k*(2*C) + cc], acc);
        }
        sp[b][k][c4] = acc;
    }
    __syncthreads();
    if (t < BB*32) {
        int b = t >> 5, k = t & 31;
        float g = sp[b][k][0] + sp[b][k][1] + sp[b][k][2] + sp[b][k][3];
        float sig = 1.f / (1.f + expf(-g));
        sg[b][k] = g * sig;            // SiLU
    }
    __syncthreads();
    if (t < BB*2) {
        int b = t >> 1, j = t & 1;
        float acc = g2b[j];
        #pragma unroll
        for (int k = 0; k < 32; k++) acc = fmaf(sg[b][k], g2[j*32 + k], acc);
        sl[b][j] = acc;
    }
    __syncthreads();
    if (t < BB) {
        float a = sl[t][0], b2 = sl[t][1];
        float m = fmaxf(a, b2);
        float e0 = expf(a - m), e1 = expf(b2 - m);
        float inv = 1.f / (e0 + e1);
        g_gate[t*2 + 0] = e0 * inv;
        g_gate[t*2 + 1] = e1 * inv;
    }
}

// ---------------- K3: gate-blend + 1x1 GEMM + residual, f32x2 FMA path ---------------
// out[b,o,p] = x * (0.5 + 0.5*(sum_c fw[o,c]*(wh*h + wv*v) + fb[o]))
__device__ __forceinline__ unsigned long long ffma2(unsigned long long a,
                                                    unsigned long long b,
                                                    unsigned long long c) {
    unsigned long long d;
    asm("fma.rn.f32x2 %0, %1, %2, %3;" : "=l"(d) : "l"(a), "l"(b), "l"(c));
    return d;
}

__global__ void __launch_bounds__(256) k3_fuse(const float* __restrict__ x,
                                               const float* __restrict__ fw,
                                               const float* __restrict__ fb,
                                               float* __restrict__ out) {
    int blk = blockIdx.x;                  // BB * (HW/128)
    int pt = blk % (HW/128);
    int b  = blk / (HW/128);
    int p0 = pt * 128;

    __shared__ unsigned long long sW2[32][128];  // (w,w) pairs, col XOR-swizzled by cl
    __shared__ float sA[32][128];                // [c_local][pixel]
    int t = threadIdx.x;
    int tp = t & 15, to = t >> 4;
    float wh = g_gate[b*2 + 0], wv = g_gate[b*2 + 1];

    unsigned long long acc2[8][4];
    #pragma unroll
    for (int j = 0; j < 8; j++)
        #pragma unroll
        for (int i = 0; i < 4; i++) acc2[j][i] = 0ULL;

    for (int kk = 0; kk < C; kk += 32) {
        __syncthreads();
        // W chunk: duplicate into both f32x2 lanes; XOR swizzle kills STS conflicts
        for (int idx = t; idx < 32*128; idx += 256) {
            int o = idx >> 5, cl = idx & 31;
            unsigned int u = __float_as_uint(fw[o*C + kk + cl]);
            sW2[cl][o ^ cl] = ((unsigned long long)u << 32) | u;
        }
        // A chunk: gated blend (coalesced along pixels)
        for (int idx = t; idx < 32*128; idx += 256) {
            int cl = idx >> 7, p = idx & 127;
            size_t gi = ((size_t)(b*C + kk + cl))*HW + p0 + p;
            sA[cl][p] = fmaf(wh, g_h[gi], wv * g_v[gi]);
        }
        __syncthreads();
        #pragma unroll
        for (int cl = 0; cl < 32; cl++) {
            const unsigned long long* pA =
                (const unsigned long long*)&sA[cl][0];
            unsigned long long af2[4];
            #pragma unroll
            for (int i = 0; i < 4; i++) af2[i] = pA[tp + 16*i];   // pixel pairs
            #pragma unroll
            for (int j = 0; j < 8; j++) {
                unsigned long long wf2 = sW2[cl][(to + 16*j) ^ cl];
                #pragma unroll
                for (int i = 0; i < 4; i++)
                    acc2[j][i] = ffma2(wf2, af2[i], acc2[j][i]);
            }
        }
    }

    #pragma unroll
    for (int j = 0; j < 8; j++) {
        int o = to + 16*j;
        float bo = fb[o];
        size_t rowbase = ((size_t)(b*C + o))*HW + p0;
        #pragma unroll
        for (int i = 0; i < 4; i++) {
            int pl = 2*(tp + 16*i);
            float2 xv = *(const float2*)(x + rowbase + pl);
            float alo = __uint_as_float((unsigned int)(acc2[j][i] & 0xffffffffu));
            float ahi = __uint_as_float((unsigned int)(acc2[j][i] >> 32));
            float2 o2;
            o2.x = xv.x * (0.5f + 0.5f*(alo + bo));
            o2.y = xv.y * (0.5f + 0.5f*(ahi + bo));
            *(float2*)(out + rowbase + pl) = o2;
        }
    }
}

// ---------------- launch -------------------------------------------------------------
extern "C" void kernel_launch(void* const* d_in, const int* in_sizes, int n_in,
                              void* d_out, int out_size) {
    const float* x   = (const float*)d_in[0];
    const float* h1  = (const float*)d_in[1];
    const float* h2  = (const float*)d_in[2];
    const float* v1  = (const float*)d_in[3];
    const float* v2  = (const float*)d_in[4];
    const float* g1  = (const float*)d_in[5];
    const float* g2  = (const float*)d_in[6];
    const float* g2b = (const float*)d_in[7];
    const float* fw  = (const float*)d_in[8];
    const float* fb  = (const float*)d_in[9];
    float* out = (float*)d_out;

    k1_conv<<<GRID_H + GRID_V, 256>>>(x, h1, h2, v1, v2);
    k2_gate<<<1, 512>>>(g1, g2, g2b);
    k3_fuse<<<BB*(HW/128), 256>>>(x, fw, fb, out);
}

// round 6
// speedup vs baseline: 1.8905x; 1.5422x over previous
#include <cuda_runtime.h>
#include <cuda_bf16.h>
#include <math.h>

#define BB 4
#define C 128
#define H 256
#define W 256
#define HW (H*W)

#define GRID_H (BB*C*(H/8))            // 16384: 1 warp = 1 row
#define GRID_V (BB*C*(H/64)*(W/32))    // 16384: 64x32 tile, 8 rows/thread

// ---------------- scratch (device globals; no allocations allowed) ----------------
__device__ __align__(16) __nv_bfloat16 g_h[(size_t)BB*C*HW];   // 64 MB
__device__ __align__(16) __nv_bfloat16 g_v[(size_t)BB*C*HW];   // 64 MB
__device__ __align__(16) __nv_bfloat16 g_fwb[C*C];
__device__ float g_hpart[BB*C*32];
__device__ float g_vpart[BB*C*32];
__device__ float g_gate[BB*2];

// ---------------- K1: both directional two-stage convs ------------------------------
__global__ void __launch_bounds__(256) k1_conv(const float* __restrict__ x,
                                               const float* __restrict__ h1w,
                                               const float* __restrict__ h2w,
                                               const float* __restrict__ v1w,
                                               const float* __restrict__ v2w) {
    int blk = blockIdx.x;
    int t = threadIdx.x;
    __shared__ float ssum[8];
    float thread_sum;
    int partIdx;
    bool isH = (blk < GRID_H);

    if (isH) {
        // -------- horizontal: 1 warp = 1 row, 8 contiguous px/thread ------------
        int rowblk = blk & 31;
        int bc = blk >> 5;
        int c = bc & (C - 1);
        int warp = t >> 5, lane = t & 31;
        int row = rowblk*8 + warp;
        const float* xr = x + (size_t)bc*HW + (size_t)row*W;
        int p0 = lane * 8;

        float w1[5], w2[7];
        #pragma unroll
        for (int i = 0; i < 5; i++) w1[i] = h1w[c*5 + i];
        #pragma unroll
        for (int j = 0; j < 7; j++) w2[j] = h2w[c*7 + j];

        float win[32];                 // x[p0-12 .. p0+19], zero padded
        #pragma unroll
        for (int i = 0; i < 8; i++) {
            int base = p0 - 12 + 4*i;
            if (base >= 0 && base + 4 <= W) {
                float4 f = *(const float4*)(xr + base);
                win[4*i] = f.x; win[4*i+1] = f.y; win[4*i+2] = f.z; win[4*i+3] = f.w;
            } else {
                #pragma unroll
                for (int j = 0; j < 4; j++) {
                    int q = base + j;
                    win[4*i + j] = (q >= 0 && q < W) ? xr[q] : 0.f;
                }
            }
        }
        float s1[26];                  // stage1 at q = p0-9+k, zero outside [0,W)
        #pragma unroll
        for (int k = 0; k < 26; k++) {
            int q = p0 - 9 + k;
            float s = 0.f;
            if (q >= 0 && q < W) {
                #pragma unroll
                for (int i = 0; i < 5; i++) s = fmaf(w1[i], win[k + 1 + i], s);
            }
            s1[k] = s;
        }
        __nv_bfloat16 ob[8];
        thread_sum = 0.f;
        #pragma unroll
        for (int d = 0; d < 8; d++) {
            float a = 0.f;
            #pragma unroll
            for (int j = 0; j < 7; j++) a = fmaf(w2[j], s1[d + 3*j], a);
            thread_sum += a;
            ob[d] = __float2bfloat16(a);
        }
        *(uint4*)(g_h + (size_t)bc*HW + (size_t)row*W + p0) = *(uint4*)ob;
        partIdx = bc*32 + rowblk;
    } else {
        // -------- vertical: 64x32 tile, 8 rows/thread ----------------------------
        int blk2 = blk - GRID_H;
        int xt = blk2 & 7;
        int yt = (blk2 >> 3) & 3;
        int bc = blk2 >> 5;
        int c = bc & (C - 1);
        int tx = t & 31, ty = t >> 5;
        int col = xt*32 + tx;
        int y0 = yt*64 + ty*8;
        const float* xc = x + (size_t)bc*HW + col;

        float w1[5], w2[7];
        #pragma unroll
        for (int i = 0; i < 5; i++) w1[i] = v1w[c*5 + i];
        #pragma unroll
        for (int j = 0; j < 7; j++) w2[j] = v2w[c*7 + j];

        float win[30];
        #pragma unroll
        for (int m = 0; m < 30; m++) {
            int gy = y0 - 11 + m;
            win[m] = (gy >= 0 && gy < H) ? xc[gy*W] : 0.f;
        }
        float s1[26];
        #pragma unroll
        for (int k = 0; k < 26; k++) {
            int gy = y0 - 9 + k;
            float s = 0.f;
            if (gy >= 0 && gy < H) {
                #pragma unroll
                for (int i = 0; i < 5; i++) s = fmaf(w1[i], win[k + i], s);
            }
            s1[k] = s;
        }
        __nv_bfloat16* vpb = g_v + (size_t)bc*HW + col;
        thread_sum = 0.f;
        #pragma unroll
        for (int d = 0; d < 8; d++) {
            float a = 0.f;
            #pragma unroll
            for (int j = 0; j < 7; j++) a = fmaf(w2[j], s1[d + 3*j], a);
            vpb[(y0 + d)*W] = __float2bfloat16(a);
            thread_sum += a;
        }
        partIdx = bc*32 + (yt*8 + xt);
    }

    float s = thread_sum;
    #pragma unroll
    for (int off = 16; off; off >>= 1) s += __shfl_down_sync(0xffffffffu, s, off);
    if ((t & 31) == 0) ssum[t >> 5] = s;
    __syncthreads();
    if (t == 0) {
        float tot = 0.f;
        #pragma unroll
        for (int i = 0; i < 8; i++) tot += ssum[i];
        if (isH) g_hpart[partIdx] = tot;
        else     g_vpart[partIdx] = tot;
    }
}

// ---------------- K2: gate MLP + softmax + fw->bf16 conversion -----------------------
__global__ void __launch_bounds__(512) k2_gate(const float* __restrict__ g1,
                                               const float* __restrict__ g2,
                                               const float* __restrict__ g2b,
                                               const float* __restrict__ fw) {
    __shared__ float shs[BB*C];
    __shared__ float svs[BB*C];
    __shared__ float sp[BB][32][4];
    __shared__ float sg[BB][32];
    __shared__ float sl[BB][2];
    int t = threadIdx.x;

    // fw -> bf16 (for K3)
    for (int i = t; i < C*C; i += 512) g_fwb[i] = __float2bfloat16(fw[i]);

    // phase 1: reduce 32 partials per (b,c)
    {
        int bc = t;                    // 512 == BB*C
        float s = 0.f;
        #pragma unroll 8
        for (int i = 0; i < 32; i++) s += g_hpart[bc*32 + i];
        shs[bc] = s;
        s = 0.f;
        #pragma unroll 8
        for (int i = 0; i < 32; i++) s += g_vpart[bc*32 + i];
        svs[bc] = s;
    }
    __syncthreads();
    {
        int b = t >> 7, k = (t >> 2) & 31, c4 = t & 3;
        const float inv = 1.f / 65536.f;
        float acc = 0.f;
        int cc0 = c4 * 64;
        #pragma unroll 8
        for (int cc = cc0; cc < cc0 + 64; cc++) {
            float p = (cc < C ? shs[b*C + cc] : svs[b*C + cc - C]) * inv;
            acc = fmaf(p, g1[k*(2*C) + cc], acc);
        }
        sp[b][k][c4] = acc;
    }
    __syncthreads();
    if (t < BB*32) {
        int b = t >> 5, k = t & 31;
        float g = sp[b][k][0] + sp[b][k][1] + sp[b][k][2] + sp[b][k][3];
        float sig = 1.f / (1.f + expf(-g));
        sg[b][k] = g * sig;
    }
    __syncthreads();
    if (t < BB*2) {
        int b = t >> 1, j = t & 1;
        float acc = g2b[j];
        #pragma unroll
        for (int k = 0; k < 32; k++) acc = fmaf(sg[b][k], g2[j*32 + k], acc);
        sl[b][j] = acc;
    }
    __syncthreads();
    if (t < BB) {
        float a = sl[t][0], b2 = sl[t][1];
        float m = fmaxf(a, b2);
        float e0 = expf(a - m), e1 = expf(b2 - m);
        float inv = 1.f / (e0 + e1);
        g_gate[t*2 + 0] = e0 * inv;
        g_gate[t*2 + 1] = e1 * inv;
    }
}

// ---------------- K3: gate-blend + 1x1 GEMM (bf16 HMMA) + residual -------------------
// out[b,o,p] = x * (0.5 + 0.5*(sum_c fw[o,c]*(wh*h + wv*v) + fb[o]))
#define SFW_STRIDE 136     // bf16 elems per row (272B -> 4-bank stagger)
#define SB_STRIDE  72      // bf16 elems per row (144B -> 4-bank stagger)
#define SFW_BYTES  (128*SFW_STRIDE*2)   // 34816
#define SB_BYTES   (128*SB_STRIDE*2)    // 18432
#define K3_SMEM    (SFW_BYTES + SB_BYTES)

__device__ __forceinline__ void ldsm_x4(unsigned addr, unsigned &r0, unsigned &r1,
                                        unsigned &r2, unsigned &r3) {
    asm volatile("ldmatrix.sync.aligned.m8n8.x4.shared.b16 {%0,%1,%2,%3}, [%4];"
                 : "=r"(r0), "=r"(r1), "=r"(r2), "=r"(r3) : "r"(addr));
}
__device__ __forceinline__ void ldsm_x4t(unsigned addr, unsigned &r0, unsigned &r1,
                                         unsigned &r2, unsigned &r3) {
    asm volatile("ldmatrix.sync.aligned.m8n8.x4.trans.shared.b16 {%0,%1,%2,%3}, [%4];"
                 : "=r"(r0), "=r"(r1), "=r"(r2), "=r"(r3) : "r"(addr));
}
__device__ __forceinline__ void mma16816(float* d, const unsigned* a,
                                         unsigned b0, unsigned b1) {
    asm volatile("mma.sync.aligned.m16n8k16.row.col.f32.bf16.bf16.f32 "
                 "{%0,%1,%2,%3}, {%4,%5,%6,%7}, {%8,%9}, {%0,%1,%2,%3};"
                 : "+f"(d[0]), "+f"(d[1]), "+f"(d[2]), "+f"(d[3])
                 : "r"(a[0]), "r"(a[1]), "r"(a[2]), "r"(a[3]), "r"(b0), "r"(b1));
}

__global__ void __launch_bounds__(256) k3_fuse(const float* __restrict__ x,
                                               const float* __restrict__ fb,
                                               float* __restrict__ out) {
    extern __shared__ __align__(16) char sm3[];
    __nv_bfloat16* sFW = (__nv_bfloat16*)sm3;                 // [128][136]
    __nv_bfloat16* sB  = (__nv_bfloat16*)(sm3 + SFW_BYTES);   // [128][72]

    int blk = blockIdx.x;                  // BB * (HW/64)
    int pt = blk & (HW/64 - 1);
    int b  = blk / (HW/64);
    int p0 = pt * 64;
    int t = threadIdx.x;
    float wh = g_gate[b*2 + 0], wv = g_gate[b*2 + 1];

    // stage fw (bf16) into smem
    for (int idx = t; idx < 4096; idx += 256) {
        int o = idx >> 5, cq = idx & 31;
        uint2 vv = *(const uint2*)(g_fwb + o*128 + cq*4);
        *(uint2*)(sFW + o*SFW_STRIDE + cq*4) = vv;
    }
    // stage blended B tile: 128c x 64px bf16
    for (int idx = t; idx < 2048; idx += 256) {
        int cc = idx >> 4, pq = idx & 15;
        size_t gi = ((size_t)(b*C + cc))*HW + p0 + pq*4;
        uint2 hu = *(const uint2*)(g_h + gi);
        uint2 vu = *(const uint2*)(g_v + gi);
        __nv_bfloat162 h0 = *(__nv_bfloat162*)&hu.x, h1 = *(__nv_bfloat162*)&hu.y;
        __nv_bfloat162 v0 = *(__nv_bfloat162*)&vu.x, v1 = *(__nv_bfloat162*)&vu.y;
        float b0 = wh*__bfloat162float(h0.x) + wv*__bfloat162float(v0.x);
        float b1 = wh*__bfloat162float(h0.y) + wv*__bfloat162float(v0.y);
        float b2 = wh*__bfloat162float(h1.x) + wv*__bfloat162float(v1.x);
        float b3 = wh*__bfloat162float(h1.y) + wv*__bfloat162float(v1.y);
        uint2 ov;
        __nv_bfloat162 o0 = __floats2bfloat162_rn(b0, b1);
        __nv_bfloat162 o1 = __floats2bfloat162_rn(b2, b3);
        ov.x = *(unsigned*)&o0; ov.y = *(unsigned*)&o1;
        *(uint2*)(sB + cc*SB_STRIDE + pq*4) = ov;
    }
    __syncthreads();

    int w = t >> 5, l = t & 31;
    unsigned sFWu = (unsigned)__cvta_generic_to_shared(sFW);
    unsigned sBu  = (unsigned)__cvta_generic_to_shared(sB);

    float acc[8][4];
    #pragma unroll
    for (int n = 0; n < 8; n++)
        #pragma unroll
        for (int i = 0; i < 4; i++) acc[n][i] = 0.f;

    int aRow = 16*w + (l & 15);
    int aColHalf = (l >> 4) * 8;
    int bRowLocal = (l & 7) + (((l >> 3) & 1) << 3);
    int bColHalf = (l >> 4) * 8;

    #pragma unroll
    for (int kk = 0; kk < 8; kk++) {
        unsigned a[4];
        unsigned aAddr = sFWu + (unsigned)(aRow*SFW_STRIDE + kk*16 + aColHalf)*2u;
        ldsm_x4(aAddr, a[0], a[1], a[2], a[3]);
        #pragma unroll
        for (int nn = 0; nn < 4; nn++) {
            unsigned b0, b1, b2, b3;
            unsigned bAddr = sBu + (unsigned)((kk*16 + bRowLocal)*SB_STRIDE
                                              + nn*16 + bColHalf)*2u;
            ldsm_x4t(bAddr, b0, b1, b2, b3);
            mma16816(acc[2*nn],     a, b0, b1);
            mma16816(acc[2*nn + 1], a, b2, b3);
        }
    }

    // epilogue: out = x * (0.5 + 0.5*(acc + fb))
    int r0 = 16*w + (l >> 2);
    float fb0 = fb[r0], fb1 = fb[r0 + 8];
    int pxoff = p0 + 2*(l & 3);
    #pragma unroll
    for (int nt = 0; nt < 8; nt++) {
        int px = pxoff + nt*8;
        size_t base0 = ((size_t)(b*C + r0))*HW + px;
        float2 xv0 = *(const float2*)(x + base0);
        float2 o0;
        o0.x = xv0.x * (0.5f + 0.5f*(acc[nt][0] + fb0));
        o0.y = xv0.y * (0.5f + 0.5f*(acc[nt][1] + fb0));
        *(float2*)(out + base0) = o0;
        size_t base1 = base0 + (size_t)8*HW;
        float2 xv1 = *(const float2*)(x + base1);
        float2 o1;
        o1.x = xv1.x * (0.5f + 0.5f*(acc[nt][2] + fb1));
        o1.y = xv1.y * (0.5f + 0.5f*(acc[nt][3] + fb1));
        *(float2*)(out + base1) = o1;
    }
}

// ---------------- launch -------------------------------------------------------------
extern "C" void kernel_launch(void* const* d_in, const int* in_sizes, int n_in,
                              void* d_out, int out_size) {
    const float* x   = (const float*)d_in[0];
    const float* h1  = (const float*)d_in[1];
    const float* h2  = (const float*)d_in[2];
    const float* v1  = (const float*)d_in[3];
    const float* v2  = (const float*)d_in[4];
    const float* g1  = (const float*)d_in[5];
    const float* g2  = (const float*)d_in[6];
    const float* g2b = (const float*)d_in[7];
    const float* fw  = (const float*)d_in[8];
    const float* fb  = (const float*)d_in[9];
    float* out = (float*)d_out;

    static int smem_set = 0;
    if (!smem_set) {
        cudaFuncSetAttribute(k3_fuse, cudaFuncAttributeMaxDynamicSharedMemorySize,
                             K3_SMEM);
        smem_set = 1;
    }

    k1_conv<<<GRID_H + GRID_V, 256>>>(x, h1, h2, v1, v2);
    k2_gate<<<1, 512>>>(g1, g2, g2b, fw);
    k3_fuse<<<BB*(HW/64), 256, K3_SMEM>>>(x, fb, out);
}

// round 7
// speedup vs baseline: 2.6181x; 1.3849x over previous
#include <cuda_runtime.h>
#include <cuda_bf16.h>
#include <math.h>

#define BB 4
#define C 128
#define H 256
#define W 256
#define HW (H*W)

#define GRID_H (BB*C*(H/8))            // 16384: 1 warp = 1 row
#define GRID_V (BB*C*(H/64)*(W/32))    // 16384: 64x32 tile, 8 rows/thread

// ---------------- scratch (device globals; no allocations allowed) ----------------
__device__ __align__(16) __nv_bfloat16 g_h[(size_t)BB*C*HW];   // 64 MB
__device__ __align__(16) __nv_bfloat16 g_v[(size_t)BB*C*HW];   // 64 MB
__device__ __align__(16) __nv_bfloat16 g_fwb[C*C];
__device__ float g_hpart[BB*C*32];
__device__ float g_vpart[BB*C*32];
__device__ float g_gate[BB*2];

// ---------------- K1: both directional two-stage convs ------------------------------
__global__ void __launch_bounds__(256) k1_conv(const float* __restrict__ x,
                                               const float* __restrict__ h1w,
                                               const float* __restrict__ h2w,
                                               const float* __restrict__ v1w,
                                               const float* __restrict__ v2w) {
    int blk = blockIdx.x;
    int t = threadIdx.x;
    __shared__ float ssum[8];
    float thread_sum;
    int partIdx;
    bool isH = (blk < GRID_H);

    if (isH) {
        // -------- horizontal: 1 warp = 1 row, 8 px/thread, shfl-composed stages ----
        int rowblk = blk & 31;
        int bc = blk >> 5;
        int c = bc & (C - 1);
        int warp = t >> 5, lane = t & 31;
        int row = rowblk*8 + warp;
        const float* xr = x + (size_t)bc*HW + (size_t)row*W;
        int p0 = lane * 8;

        float w1[5], w2[7];
        #pragma unroll
        for (int i = 0; i < 5; i++) w1[i] = h1w[c*5 + i];
        #pragma unroll
        for (int j = 0; j < 7; j++) w2[j] = h2w[c*7 + j];

        // window x[p0-2 .. p0+9] via 4 clamped float4 loads + lane-pred zeroes
        int bl = p0 - 4;
        float4 c0 = *(const float4*)(xr + (bl < 0 ? 0 : bl));
        float4 c1 = *(const float4*)(xr + p0);
        float4 c1b = *(const float4*)(xr + p0 + 4);
        int br = p0 + 8;
        float4 c2 = *(const float4*)(xr + (br > W-4 ? W-4 : br));
        float wq[12];                  // wq[m] = x[p0-2+m] (zero padded)
        wq[0] = (lane > 0) ? c0.z : 0.f;
        wq[1] = (lane > 0) ? c0.w : 0.f;
        wq[2] = c1.x; wq[3] = c1.y; wq[4] = c1.z; wq[5] = c1.w;
        wq[6] = c1b.x; wq[7] = c1b.y; wq[8] = c1b.z; wq[9] = c1b.w;
        wq[10] = (lane < 31) ? c2.x : 0.f;
        wq[11] = (lane < 31) ? c2.y : 0.f;

        // stage1 for OWN 8 pixels only: s1[k] = sum_i w1[i]*x[p0+k-2+i]
        float s1[8];
        #pragma unroll
        for (int k = 0; k < 8; k++) {
            float s = 0.f;
            #pragma unroll
            for (int i = 0; i < 5; i++) s = fmaf(w1[i], wq[k + i], s);
            s1[k] = s;
        }

        // assemble 26-wide stage2 window wf[k] = s1 at q = p0-9+k (zero outside [0,W))
        float wf[26];
        {
            float vv = __shfl_up_sync(0xffffffffu, s1[7], 2);
            wf[0] = (lane >= 2) ? vv : 0.f;
        }
        #pragma unroll
        for (int k = 0; k < 8; k++) {
            float vv = __shfl_up_sync(0xffffffffu, s1[k], 1);
            wf[1 + k] = (lane >= 1) ? vv : 0.f;
        }
        #pragma unroll
        for (int k = 0; k < 8; k++) wf[9 + k] = s1[k];
        #pragma unroll
        for (int k = 0; k < 8; k++) {
            float vv = __shfl_down_sync(0xffffffffu, s1[k], 1);
            wf[17 + k] = (lane <= 30) ? vv : 0.f;
        }
        {
            float vv = __shfl_down_sync(0xffffffffu, s1[0], 2);
            wf[25] = (lane <= 29) ? vv : 0.f;
        }

        __nv_bfloat16 ob[8];
        thread_sum = 0.f;
        #pragma unroll
        for (int d = 0; d < 8; d++) {
            float a = 0.f;
            #pragma unroll
            for (int j = 0; j < 7; j++) a = fmaf(w2[j], wf[d + 3*j], a);
            thread_sum += a;
            ob[d] = __float2bfloat16(a);
        }
        *(uint4*)(g_h + (size_t)bc*HW + (size_t)row*W + p0) = *(uint4*)ob;
        partIdx = bc*32 + rowblk;
    } else {
        // -------- vertical: 64x32 tile, 8 rows/thread, warp-uniform fast path ------
        int blk2 = blk - GRID_H;
        int xt = blk2 & 7;
        int yt = (blk2 >> 3) & 3;
        int bc = blk2 >> 5;
        int c = bc & (C - 1);
        int tx = t & 31, ty = t >> 5;
        int col = xt*32 + tx;
        int y0 = yt*64 + ty*8;
        const float* xc = x + (size_t)bc*HW + col;

        float w1[5], w2[7];
        #pragma unroll
        for (int i = 0; i < 5; i++) w1[i] = v1w[c*5 + i];
        #pragma unroll
        for (int j = 0; j < 7; j++) w2[j] = v2w[c*7 + j];

        float s1[26];
        if (y0 >= 11 && y0 + 18 < H) {
            // interior: no guards at all
            float win[30];
            #pragma unroll
            for (int m = 0; m < 30; m++) win[m] = xc[(y0 - 11 + m)*W];
            #pragma unroll
            for (int k = 0; k < 26; k++) {
                float s = 0.f;
                #pragma unroll
                for (int i = 0; i < 5; i++) s = fmaf(w1[i], win[k + i], s);
                s1[k] = s;
            }
        } else {
            float win[30];
            #pragma unroll
            for (int m = 0; m < 30; m++) {
                int gy = y0 - 11 + m;
                win[m] = (gy >= 0 && gy < H) ? xc[gy*W] : 0.f;
            }
            #pragma unroll
            for (int k = 0; k < 26; k++) {
                int gy = y0 - 9 + k;
                float s = 0.f;
                if (gy >= 0 && gy < H) {
                    #pragma unroll
                    for (int i = 0; i < 5; i++) s = fmaf(w1[i], win[k + i], s);
                }
                s1[k] = s;
            }
        }
        __nv_bfloat16* vpb = g_v + (size_t)bc*HW + col;
        thread_sum = 0.f;
        #pragma unroll
        for (int d = 0; d < 8; d++) {
            float a = 0.f;
            #pragma unroll
            for (int j = 0; j < 7; j++) a = fmaf(w2[j], s1[d + 3*j], a);
            vpb[(y0 + d)*W] = __float2bfloat16(a);
            thread_sum += a;
        }
        partIdx = bc*32 + (yt*8 + xt);
    }

    float s = thread_sum;
    #pragma unroll
    for (int off = 16; off; off >>= 1) s += __shfl_down_sync(0xffffffffu, s, off);
    if ((t & 31) == 0) ssum[t >> 5] = s;
    __syncthreads();
    if (t == 0) {
        float tot = 0.f;
        #pragma unroll
        for (int i = 0; i < 8; i++) tot += ssum[i];
        if (isH) g_hpart[partIdx] = tot;
        else     g_vpart[partIdx] = tot;
    }
}

// ---------------- K2: gate MLP + softmax + fw->bf16 conversion -----------------------
__global__ void __launch_bounds__(512) k2_gate(const float* __restrict__ g1,
                                               const float* __restrict__ g2,
                                               const float* __restrict__ g2b,
                                               const float* __restrict__ fw) {
    __shared__ float shs[BB*C];
    __shared__ float svs[BB*C];
    __shared__ float sp[BB][32][4];
    __shared__ float sg[BB][32];
    __shared__ float sl[BB][2];
    int t = threadIdx.x;

    for (int i = t; i < C*C; i += 512) g_fwb[i] = __float2bfloat16(fw[i]);

    {
        int bc = t;
        float s = 0.f;
        #pragma unroll 8
        for (int i = 0; i < 32; i++) s += g_hpart[bc*32 + i];
        shs[bc] = s;
        s = 0.f;
        #pragma unroll 8
        for (int i = 0; i < 32; i++) s += g_vpart[bc*32 + i];
        svs[bc] = s;
    }
    __syncthreads();
    {
        int b = t >> 7, k = (t >> 2) & 31, c4 = t & 3;
        const float inv = 1.f / 65536.f;
        float acc = 0.f;
        int cc0 = c4 * 64;
        #pragma unroll 8
        for (int cc = cc0; cc < cc0 + 64; cc++) {
            float p = (cc < C ? shs[b*C + cc] : svs[b*C + cc - C]) * inv;
            acc = fmaf(p, g1[k*(2*C) + cc], acc);
        }
        sp[b][k][c4] = acc;
    }
    __syncthreads();
    if (t < BB*32) {
        int b = t >> 5, k = t & 31;
        float g = sp[b][k][0] + sp[b][k][1] + sp[b][k][2] + sp[b][k][3];
        float sig = 1.f / (1.f + expf(-g));
        sg[b][k] = g * sig;
    }
    __syncthreads();
    if (t < BB*2) {
        int b = t >> 1, j = t & 1;
        float acc = g2b[j];
        #pragma unroll
        for (int k = 0; k < 32; k++) acc = fmaf(sg[b][k], g2[j*32 + k], acc);
        sl[b][j] = acc;
    }
    __syncthreads();
    if (t < BB) {
        float a = sl[t][0], b2 = sl[t][1];
        float m = fmaxf(a, b2);
        float e0 = expf(a - m), e1 = expf(b2 - m);
        float inv = 1.f / (e0 + e1);
        g_gate[t*2 + 0] = e0 * inv;
        g_gate[t*2 + 1] = e1 * inv;
    }
}

// ---------------- K3: split-GEMM (wh*fw@h + wv*fw@v), cp.async staging --------------
#define SFW_STRIDE 136     // bf16 elems per row (272B)
#define SB_STRIDE  72      // bf16 elems per row (144B)
#define SFW_BYTES  (128*SFW_STRIDE*2)   // 34816
#define SB_BYTES   (128*SB_STRIDE*2)    // 18432
#define K3_SMEM    (SFW_BYTES + 2*SB_BYTES)

__device__ __forceinline__ void cpa16(unsigned dst, const void* src) {
    asm volatile("cp.async.cg.shared.global [%0], [%1], 16;" :: "r"(dst), "l"(src));
}
__device__ __forceinline__ void ldsm_x4(unsigned addr, unsigned &r0, unsigned &r1,
                                        unsigned &r2, unsigned &r3) {
    asm volatile("ldmatrix.sync.aligned.m8n8.x4.shared.b16 {%0,%1,%2,%3}, [%4];"
                 : "=r"(r0), "=r"(r1), "=r"(r2), "=r"(r3) : "r"(addr));
}
__device__ __forceinline__ void ldsm_x4t(unsigned addr, unsigned &r0, unsigned &r1,
                                         unsigned &r2, unsigned &r3) {
    asm volatile("ldmatrix.sync.aligned.m8n8.x4.trans.shared.b16 {%0,%1,%2,%3}, [%4];"
                 : "=r"(r0), "=r"(r1), "=r"(r2), "=r"(r3) : "r"(addr));
}
__device__ __forceinline__ void mma16816(float* d, const unsigned* a,
                                         unsigned b0, unsigned b1) {
    asm volatile("mma.sync.aligned.m16n8k16.row.col.f32.bf16.bf16.f32 "
                 "{%0,%1,%2,%3}, {%4,%5,%6,%7}, {%8,%9}, {%0,%1,%2,%3};"
                 : "+f"(d[0]), "+f"(d[1]), "+f"(d[2]), "+f"(d[3])
                 : "r"(a[0]), "r"(a[1]), "r"(a[2]), "r"(a[3]), "r"(b0), "r"(b1));
}

__global__ void __launch_bounds__(256) k3_fuse(const float* __restrict__ x,
                                               const float* __restrict__ fb,
                                               float* __restrict__ out) {
    extern __shared__ __align__(16) char sm3[];
    char* sFW = sm3;
    char* sH  = sm3 + SFW_BYTES;
    char* sV  = sH + SB_BYTES;
    unsigned sFWu = (unsigned)__cvta_generic_to_shared(sFW);
    unsigned sHu  = (unsigned)__cvta_generic_to_shared(sH);
    unsigned sVu  = (unsigned)__cvta_generic_to_shared(sV);

    int blk = blockIdx.x;                  // BB * (HW/64)
    int pt = blk & (HW/64 - 1);
    int b  = blk / (HW/64);
    int p0 = pt * 64;
    int t = threadIdx.x;
    float wh = g_gate[b*2 + 0], wv = g_gate[b*2 + 1];

    // stage fw: 128 rows x 256B, 16B chunks
    #pragma unroll
    for (int rep = 0; rep < 8; rep++) {
        int idx = t + rep*256;
        int row = idx >> 4, cq = idx & 15;
        cpa16(sFWu + row*(SFW_STRIDE*2) + cq*16, g_fwb + row*128 + cq*8);
    }
    // stage h, v: 128 c-rows x 128B each, 16B chunks
    #pragma unroll
    for (int rep = 0; rep < 4; rep++) {
        int idx = t + rep*256;
        int cc = idx >> 3, q = idx & 7;
        size_t gi = ((size_t)(b*C + cc))*HW + p0 + q*8;
        unsigned doff = cc*(SB_STRIDE*2) + q*16;
        cpa16(sHu + doff, g_h + gi);
        cpa16(sVu + doff, g_v + gi);
    }
    asm volatile("cp.async.commit_group;");
    asm volatile("cp.async.wait_group 0;");
    __syncthreads();

    int w = t >> 5, l = t & 31;
    float accH[8][4], accV[8][4];
    #pragma unroll
    for (int n = 0; n < 8; n++)
        #pragma unroll
        for (int i = 0; i < 4; i++) { accH[n][i] = 0.f; accV[n][i] = 0.f; }

    int aRow = 16*w + (l & 15);
    int aColHalf = (l >> 4) * 8;
    int bRowLocal = (l & 7) + (((l >> 3) & 1) << 3);
    int bColHalf = (l >> 4) * 8;

    #pragma unroll
    for (int kk = 0; kk < 8; kk++) {
        unsigned a[4];
        unsigned aAddr = sFWu + (unsigned)(aRow*SFW_STRIDE + kk*16 + aColHalf)*2u;
        ldsm_x4(aAddr, a[0], a[1], a[2], a[3]);
        #pragma unroll
        for (int nn = 0; nn < 4; nn++) {
            unsigned boff = (unsigned)((kk*16 + bRowLocal)*SB_STRIDE
                                       + nn*16 + bColHalf)*2u;
            unsigned b0, b1, b2, b3;
            ldsm_x4t(sHu + boff, b0, b1, b2, b3);
            mma16816(accH[2*nn],     a, b0, b1);
            mma16816(accH[2*nn + 1], a, b2, b3);
            ldsm_x4t(sVu + boff, b0, b1, b2, b3);
            mma16816(accV[2*nn],     a, b0, b1);
            mma16816(accV[2*nn + 1], a, b2, b3);
        }
    }

    // epilogue: a = wh*accH + wv*accV; out = x * (0.5 + 0.5*(a + fb))
    int r0 = 16*w + (l >> 2);
    float fb0 = fb[r0], fb1 = fb[r0 + 8];
    int pxoff = p0 + 2*(l & 3);
    #pragma unroll
    for (int nt = 0; nt < 8; nt++) {
        int px = pxoff + nt*8;
        size_t base0 = ((size_t)(b*C + r0))*HW + px;
        float2 xv0 = *(const float2*)(x + base0);
        float a0 = fmaf(wh, accH[nt][0], wv * accV[nt][0]);
        float a1 = fmaf(wh, accH[nt][1], wv * accV[nt][1]);
        float2 o0;
        o0.x = xv0.x * (0.5f + 0.5f*(a0 + fb0));
        o0.y = xv0.y * (0.5f + 0.5f*(a1 + fb0));
        *(float2*)(out + base0) = o0;
        size_t base1 = base0 + (size_t)8*HW;
        float2 xv1 = *(const float2*)(x + base1);
        float a2 = fmaf(wh, accH[nt][2], wv * accV[nt][2]);
        float a3 = fmaf(wh, accH[nt][3], wv * accV[nt][3]);
        float2 o1;
        o1.x = xv1.x * (0.5f + 0.5f*(a2 + fb1));
        o1.y = xv1.y * (0.5f + 0.5f*(a3 + fb1));
        *(float2*)(out + base1) = o1;
    }
}

// ---------------- launch -------------------------------------------------------------
extern "C" void kernel_launch(void* const* d_in, const int* in_sizes, int n_in,
                              void* d_out, int out_size) {
    const float* x   = (const float*)d_in[0];
    const float* h1  = (const float*)d_in[1];
    const float* h2  = (const float*)d_in[2];
    const float* v1  = (const float*)d_in[3];
    const float* v2  = (const float*)d_in[4];
    const float* g1  = (const float*)d_in[5];
    const float* g2  = (const float*)d_in[6];
    const float* g2b = (const float*)d_in[7];
    const float* fw  = (const float*)d_in[8];
    const float* fb  = (const float*)d_in[9];
    float* out = (float*)d_out;

    static int smem_set = 0;
    if (!smem_set) {
        cudaFuncSetAttribute(k3_fuse, cudaFuncAttributeMaxDynamicSharedMemorySize,
                             K3_SMEM);
        smem_set = 1;
    }

    k1_conv<<<GRID_H + GRID_V, 256>>>(x, h1, h2, v1, v2);
    k2_gate<<<1, 512>>>(g1, g2, g2b, fw);
    k3_fuse<<<BB*(HW/64), 256, K3_SMEM>>>(x, fb, out);
}

// round 9
// speedup vs baseline: 2.9004x; 1.1078x over previous
#include <cuda_runtime.h>
#include <cuda_bf16.h>
#include <math.h>

#define BB 4
#define C 128
#define H 256
#define W 256
#define HW (H*W)

#define GRID_H (BB*C*(H/8))            // 16384: 1 warp = 1 row, 8 px/thread
#define GRID_V (BB*C*8)                // 4096: 64x128 tile, 32 rows/thread

// ---------------- scratch (device globals; no allocations allowed) ----------------
__device__ __align__(16) __nv_bfloat16 g_h[(size_t)BB*C*HW];   // 64 MB
__device__ __align__(16) __nv_bfloat16 g_v[(size_t)BB*C*HW];   // 64 MB
__device__ __align__(16) __nv_bfloat16 g_fwb[C*C];
__device__ float g_hpart[BB*C*32];
__device__ float g_vpart[BB*C*32];
__device__ float g_gate[BB*2];

// ---------------- K1: both directional two-stage convs ------------------------------
__global__ void __launch_bounds__(256) k1_conv(const float* __restrict__ x,
                                               const float* __restrict__ h1w,
                                               const float* __restrict__ h2w,
                                               const float* __restrict__ v1w,
                                               const float* __restrict__ v2w) {
    int blk = blockIdx.x;
    int t = threadIdx.x;
    __shared__ float ssum[8];
    float thread_sum;
    int partIdx;
    bool isH = (blk < GRID_H);

    if (isH) {
        // -------- horizontal: 1 warp = 1 row, 8 px/thread, shfl-composed stages ----
        int rowblk = blk & 31;
        int bc = blk >> 5;
        int c = bc & (C - 1);
        int warp = t >> 5, lane = t & 31;
        int row = rowblk*8 + warp;
        const float* xr = x + (size_t)bc*HW + (size_t)row*W;
        int p0 = lane * 8;

        float w1[5], w2[7];
        #pragma unroll
        for (int i = 0; i < 5; i++) w1[i] = h1w[c*5 + i];
        #pragma unroll
        for (int j = 0; j < 7; j++) w2[j] = h2w[c*7 + j];

        int bl = p0 - 4;
        float4 c0 = *(const float4*)(xr + (bl < 0 ? 0 : bl));
        float4 c1 = *(const float4*)(xr + p0);
        float4 c1b = *(const float4*)(xr + p0 + 4);
        int br = p0 + 8;
        float4 c2 = *(const float4*)(xr + (br > W-4 ? W-4 : br));
        float wq[12];                  // wq[m] = x[p0-2+m] (zero padded)
        wq[0] = (lane > 0) ? c0.z : 0.f;
        wq[1] = (lane > 0) ? c0.w : 0.f;
        wq[2] = c1.x; wq[3] = c1.y; wq[4] = c1.z; wq[5] = c1.w;
        wq[6] = c1b.x; wq[7] = c1b.y; wq[8] = c1b.z; wq[9] = c1b.w;
        wq[10] = (lane < 31) ? c2.x : 0.f;
        wq[11] = (lane < 31) ? c2.y : 0.f;

        float s1[8];
        #pragma unroll
        for (int k = 0; k < 8; k++) {
            float s = 0.f;
            #pragma unroll
            for (int i = 0; i < 5; i++) s = fmaf(w1[i], wq[k + i], s);
            s1[k] = s;
        }

        float wf[26];
        {
            float vv = __shfl_up_sync(0xffffffffu, s1[7], 2);
            wf[0] = (lane >= 2) ? vv : 0.f;
        }
        #pragma unroll
        for (int k = 0; k < 8; k++) {
            float vv = __shfl_up_sync(0xffffffffu, s1[k], 1);
            wf[1 + k] = (lane >= 1) ? vv : 0.f;
        }
        #pragma unroll
        for (int k = 0; k < 8; k++) wf[9 + k] = s1[k];
        #pragma unroll
        for (int k = 0; k < 8; k++) {
            float vv = __shfl_down_sync(0xffffffffu, s1[k], 1);
            wf[17 + k] = (lane <= 30) ? vv : 0.f;
        }
        {
            float vv = __shfl_down_sync(0xffffffffu, s1[0], 2);
            wf[25] = (lane <= 29) ? vv : 0.f;
        }

        __nv_bfloat16 ob[8];
        thread_sum = 0.f;
        #pragma unroll
        for (int d = 0; d < 8; d++) {
            float a = 0.f;
            #pragma unroll
            for (int j = 0; j < 7; j++) a = fmaf(w2[j], wf[d + 3*j], a);
            thread_sum += a;
            ob[d] = __float2bfloat16(a);
        }
        *(uint4*)(g_h + (size_t)bc*HW + (size_t)row*W + p0) = *(uint4*)ob;
        partIdx = bc*32 + rowblk;
    } else {
        // -------- vertical: 64x128 tile, 32 rows/thread, streaming s1 ---------------
        int blk2 = blk - GRID_H;
        int xt = blk2 & 1;
        int yt = (blk2 >> 1) & 3;
        int bc = blk2 >> 3;
        int c = bc & (C - 1);
        int tx = t & 127, ty = t >> 7;
        int col = xt*128 + tx;
        int y0 = yt*64 + ty*32;
        const float* xc = x + (size_t)bc*HW + col;

        float w1[5], w2[7];
        #pragma unroll
        for (int i = 0; i < 5; i++) w1[i] = v1w[c*5 + i];
        #pragma unroll
        for (int j = 0; j < 7; j++) w2[j] = v2w[c*7 + j];

        float acc[32];
        #pragma unroll
        for (int d = 0; d < 32; d++) acc[d] = 0.f;

        float xr[5];
        #pragma unroll
        for (int m = 0; m < 4; m++) {
            int gy = y0 - 11 + m;
            xr[m] = (gy >= 0 && gy < H) ? xc[gy*W] : 0.f;
        }
        // s1 row gy1 = y0-9+k needs x rows y0-11+k .. y0-7+k (slot (k+i)%5)
        #pragma unroll
        for (int k = 0; k < 50; k++) {
            int gy = y0 - 7 + k;
            xr[(k + 4) % 5] = (gy >= 0 && gy < H) ? xc[gy*W] : 0.f;
            float s = 0.f;
            #pragma unroll
            for (int i = 0; i < 5; i++) s = fmaf(w1[i], xr[(k + i) % 5], s);
            int gy1 = y0 - 9 + k;
            s = (gy1 >= 0 && gy1 < H) ? s : 0.f;
            #pragma unroll
            for (int j = 0; j < 7; j++) {
                int d = k - 3*j;
                if (d >= 0 && d < 32) acc[d] = fmaf(w2[j], s, acc[d]);
            }
        }
        __nv_bfloat16* vpb = g_v + (size_t)bc*HW + col;
        thread_sum = 0.f;
        #pragma unroll
        for (int d = 0; d < 32; d++) {
            vpb[(y0 + d)*W] = __float2bfloat16(acc[d]);
            thread_sum += acc[d];
        }
        partIdx = bc*32 + (yt*2 + xt);
    }

    float s = thread_sum;
    #pragma unroll
    for (int off = 16; off; off >>= 1) s += __shfl_down_sync(0xffffffffu, s, off);
    if ((t & 31) == 0) ssum[t >> 5] = s;
    __syncthreads();
    if (t == 0) {
        float tot = 0.f;
        #pragma unroll
        for (int i = 0; i < 8; i++) tot += ssum[i];
        if (isH) g_hpart[partIdx] = tot;
        else     g_vpart[partIdx] = tot;
    }
}

// ---------------- K2: gate MLP + softmax + fw->bf16 conversion -----------------------
__global__ void __launch_bounds__(512) k2_gate(const float* __restrict__ g1,
                                               const float* __restrict__ g2,
                                               const float* __restrict__ g2b,
                                               const float* __restrict__ fw) {
    __shared__ float shs[BB*C];
    __shared__ float svs[BB*C];
    __shared__ float sp[BB][32][4];
    __shared__ float sg[BB][32];
    __shared__ float sl[BB][2];
    int t = threadIdx.x;

    for (int i = t; i < C*C; i += 512) g_fwb[i] = __float2bfloat16(fw[i]);

    {
        int bc = t;
        float s = 0.f;
        #pragma unroll 8
        for (int i = 0; i < 32; i++) s += g_hpart[bc*32 + i];
        shs[bc] = s;
        s = 0.f;
        #pragma unroll
        for (int i = 0; i < 8; i++) s += g_vpart[bc*32 + i];
        svs[bc] = s;
    }
    __syncthreads();
    {
        int b = t >> 7, k = (t >> 2) & 31, c4 = t & 3;
        const float inv = 1.f / 65536.f;
        float acc = 0.f;
        int cc0 = c4 * 64;
        #pragma unroll 8
        for (int cc = cc0; cc < cc0 + 64; cc++) {
            float p = (cc < C ? shs[b*C + cc] : svs[b*C + cc - C]) * inv;
            acc = fmaf(p, g1[k*(2*C) + cc], acc);
        }
        sp[b][k][c4] = acc;
    }
    __syncthreads();
    if (t < BB*32) {
        int b = t >> 5, k = t & 31;
        float g = sp[b][k][0] + sp[b][k][1] + sp[b][k][2] + sp[b][k][3];
        float sig = 1.f / (1.f + expf(-g));
        sg[b][k] = g * sig;
    }
    __syncthreads();
    if (t < BB*2) {
        int b = t >> 1, j = t & 1;
        float acc = g2b[j];
        #pragma unroll
        for (int k = 0; k < 32; k++) acc = fmaf(sg[b][k], g2[j*32 + k], acc);
        sl[b][j] = acc;
    }
    __syncthreads();
    if (t < BB) {
        float a = sl[t][0], b2 = sl[t][1];
        float m = fmaxf(a, b2);
        float e0 = expf(a - m), e1 = expf(b2 - m);
        float inv = 1.f / (e0 + e1);
        g_gate[t*2 + 0] = e0 * inv;
        g_gate[t*2 + 1] = e1 * inv;
    }
}

// ---------------- K3: persistent split-GEMM, double-buffered cp.async pipeline -------
#define SFW_STRIDE 136     // bf16 elems per row (272B)
#define SB_STRIDE  72      // bf16 elems per row (144B)
#define SFW_BYTES  (128*SFW_STRIDE*2)   // 34816
#define SB_BYTES   (128*SB_STRIDE*2)    // 18432
#define STAGE_BYTES (2*SB_BYTES)        // H + V per buffer
#define K3_SMEM    (SFW_BYTES + 2*STAGE_BYTES)  // 108544
#define NB3 304
#define NTILES (BB*(HW/64))             // 4096

__device__ __forceinline__ void cpa16(unsigned dst, const void* src) {
    asm volatile("cp.async.cg.shared.global [%0], [%1], 16;" :: "r"(dst), "l"(src));
}
__device__ __forceinline__ void ldsm_x4(unsigned addr, unsigned &r0, unsigned &r1,
                                        unsigned &r2, unsigned &r3) {
    asm volatile("ldmatrix.sync.aligned.m8n8.x4.shared.b16 {%0,%1,%2,%3}, [%4];"
                 : "=r"(r0), "=r"(r1), "=r"(r2), "=r"(r3) : "r"(addr));
}
__device__ __forceinline__ void ldsm_x4t(unsigned addr, unsigned &r0, unsigned &r1,
                                         unsigned &r2, unsigned &r3) {
    asm volatile("ldmatrix.sync.aligned.m8n8.x4.trans.shared.b16 {%0,%1,%2,%3}, [%4];"
                 : "=r"(r0), "=r"(r1), "=r"(r2), "=r"(r3) : "r"(addr));
}
__device__ __forceinline__ void mma16816(float* d, const unsigned* a,
                                         unsigned b0, unsigned b1) {
    asm volatile("mma.sync.aligned.m16n8k16.row.col.f32.bf16.bf16.f32 "
                 "{%0,%1,%2,%3}, {%4,%5,%6,%7}, {%8,%9}, {%0,%1,%2,%3};"
                 : "+f"(d[0]), "+f"(d[1]), "+f"(d[2]), "+f"(d[3])
                 : "r"(a[0]), "r"(a[1]), "r"(a[2]), "r"(a[3]), "r"(b0), "r"(b1));
}

__device__ __forceinline__ void k3_stage(unsigned su, int tile, int t) {
    int b = tile >> 10;
    int p0 = (tile & 1023) * 64;
    #pragma unroll
    for (int rep = 0; rep < 4; rep++) {
        int idx = t + rep*256;
        int cc = idx >> 3, q = idx & 7;
        size_t gi = ((size_t)(b*C + cc))*HW + p0 + q*8;
        unsigned doff = cc*(SB_STRIDE*2) + q*16;
        cpa16(su + doff, g_h + gi);
        cpa16(su + SB_BYTES + doff, g_v + gi);
    }
}

__global__ void __launch_bounds__(256, 2) k3_fuse(const float* __restrict__ x,
                                                  const float* __restrict__ fb,
                                                  float* __restrict__ out) {
    extern __shared__ __align__(16) char sm3[];
    unsigned sFWu = (unsigned)__cvta_generic_to_shared(sm3);
    unsigned st0u = sFWu + SFW_BYTES;
    unsigned st1u = st0u + STAGE_BYTES;
    int t = threadIdx.x;
    int w = t >> 5, l = t & 31;

    // stage fw once (part of group 0)
    #pragma unroll
    for (int rep = 0; rep < 8; rep++) {
        int idx = t + rep*256;
        int row = idx >> 4, cq = idx & 15;
        cpa16(sFWu + row*(SFW_STRIDE*2) + cq*16, g_fwb + row*128 + cq*8);
    }
    int tile = blockIdx.x;
    k3_stage(st0u, tile, t);
    asm volatile("cp.async.commit_group;");

    int aRow = 16*w + (l & 15);
    int aColHalf = (l >> 4) * 8;
    int bRowLocal = (l & 7) + (((l >> 3) & 1) << 3);
    int bColHalf = (l >> 4) * 8;
    int r0 = 16*w + (l >> 2);

    for (int it = 0; tile < NTILES; tile += NB3, it++) {
        unsigned cur = (it & 1) ? st1u : st0u;
        unsigned nxt = (it & 1) ? st0u : st1u;
        int ntile = tile + NB3;
        if (ntile < NTILES) {
            k3_stage(nxt, ntile, t);
            asm volatile("cp.async.commit_group;");
            asm volatile("cp.async.wait_group 1;");
        } else {
            asm volatile("cp.async.wait_group 0;");
        }
        __syncthreads();

        int b = tile >> 10;
        int p0 = (tile & 1023) * 64;
        float wh = g_gate[b*2 + 0], wv = g_gate[b*2 + 1];
        unsigned sHu = cur, sVu = cur + SB_BYTES;

        float accH[8][4], accV[8][4];
        #pragma unroll
        for (int n = 0; n < 8; n++)
            #pragma unroll
            for (int i = 0; i < 4; i++) { accH[n][i] = 0.f; accV[n][i] = 0.f; }

        #pragma unroll
        for (int kk = 0; kk < 8; kk++) {
            unsigned a[4];
            unsigned aAddr = sFWu + (unsigned)(aRow*SFW_STRIDE + kk*16 + aColHalf)*2u;
            ldsm_x4(aAddr, a[0], a[1], a[2], a[3]);
            #pragma unroll
            for (int nn = 0; nn < 4; nn++) {
                unsigned boff = (unsigned)((kk*16 + bRowLocal)*SB_STRIDE
                                           + nn*16 + bColHalf)*2u;
                unsigned b0, b1, b2, b3;
                ldsm_x4t(sHu + boff, b0, b1, b2, b3);
                mma16816(accH[2*nn],     a, b0, b1);
                mma16816(accH[2*nn + 1], a, b2, b3);
                ldsm_x4t(sVu + boff, b0, b1, b2, b3);
                mma16816(accV[2*nn],     a, b0, b1);
                mma16816(accV[2*nn + 1], a, b2, b3);
            }
        }

        float fb0 = fb[r0], fb1 = fb[r0 + 8];
        int pxoff = p0 + 2*(l & 3);
        #pragma unroll
        for (int nt = 0; nt < 8; nt++) {
            int px = pxoff + nt*8;
            size_t base0 = ((size_t)(b*C + r0))*HW + px;
            float2 xv0 = *(const float2*)(x + base0);
            float a0 = fmaf(wh, accH[nt][0], wv * accV[nt][0]);
            float a1 = fmaf(wh, accH[nt][1], wv * accV[nt][1]);
            float2 o0;
            o0.x = xv0.x * (0.5f + 0.5f*(a0 + fb0));
            o0.y = xv0.y * (0.5f + 0.5f*(a1 + fb0));
            *(float2*)(out + base0) = o0;
            size_t base1 = base0 + (size_t)8*HW;
            float2 xv1 = *(const float2*)(x + base1);
            float a2 = fmaf(wh, accH[nt][2], wv * accV[nt][2]);
            float a3 = fmaf(wh, accH[nt][3], wv * accV[nt][3]);
            float2 o1;
            o1.x = xv1.x * (0.5f + 0.5f*(a2 + fb1));
            o1.y = xv1.y * (0.5f + 0.5f*(a3 + fb1));
            *(float2*)(out + base1) = o1;
        }
        __syncthreads();
    }
}

// ---------------- launch -------------------------------------------------------------
extern "C" void kernel_launch(void* const* d_in, const int* in_sizes, int n_in,
                              void* d_out, int out_size) {
    const float* x   = (const float*)d_in[0];
    const float* h1  = (const float*)d_in[1];
    const float* h2  = (const float*)d_in[2];
    const float* v1  = (const float*)d_in[3];
    const float* v2  = (const float*)d_in[4];
    const float* g1  = (const float*)d_in[5];
    const float* g2  = (const float*)d_in[6];
    const float* g2b = (const float*)d_in[7];
    const float* fw  = (const float*)d_in[8];
    const float* fb  = (const float*)d_in[9];
    float* out = (float*)d_out;

    static int smem_set = 0;
    if (!smem_set) {
        cudaFuncSetAttribute(k3_fuse, cudaFuncAttributeMaxDynamicSharedMemorySize,
                             K3_SMEM);
        smem_set = 1;
    }

    k1_conv<<<GRID_H + GRID_V, 256>>>(x, h1, h2, v1, v2);
    k2_gate<<<1, 512>>>(g1, g2, g2b, fw);
    k3_fuse<<<NB3, 256, K3_SMEM>>>(x, fb, out);
}

// round 10
// speedup vs baseline: 3.2968x; 1.1367x over previous
#include <cuda_runtime.h>
#include <cuda_bf16.h>
#include <math.h>

#define BB 4
#define C 128
#define H 256
#define W 256
#define HW (H*W)

#define GRID_H (BB*C*(H/8))            // 16384: 1 warp = 1 row, 8 px/thread
#define GRID_V (BB*C*8)                // 4096: 64x128 tile, 32 rows/thread

// ---------------- scratch (device globals; no allocations allowed) ----------------
__device__ __align__(16) __nv_bfloat16 g_h[(size_t)BB*C*HW];   // 64 MB
__device__ __align__(16) __nv_bfloat16 g_v[(size_t)BB*C*HW];   // 64 MB
__device__ __align__(16) __nv_bfloat16 g_fwb[C*C];
__device__ float g_hpart[BB*C*32];
__device__ float g_vpart[BB*C*32];
__device__ float g_gate[BB*2];

// ---------------- K1h: horizontal two-stage conv (1 warp = 1 row) -------------------
__global__ void __launch_bounds__(256) k1_h(const float* __restrict__ x,
                                            const float* __restrict__ h1w,
                                            const float* __restrict__ h2w) {
    int blk = blockIdx.x;
    int t = threadIdx.x;
    __shared__ float ssum[8];

    int rowblk = blk & 31;
    int bc = blk >> 5;
    int c = bc & (C - 1);
    int warp = t >> 5, lane = t & 31;
    int row = rowblk*8 + warp;
    const float* xr = x + (size_t)bc*HW + (size_t)row*W;
    int p0 = lane * 8;

    float w1[5], w2[7];
    #pragma unroll
    for (int i = 0; i < 5; i++) w1[i] = h1w[c*5 + i];
    #pragma unroll
    for (int j = 0; j < 7; j++) w2[j] = h2w[c*7 + j];

    int bl = p0 - 4;
    float4 c0 = *(const float4*)(xr + (bl < 0 ? 0 : bl));
    float4 c1 = *(const float4*)(xr + p0);
    float4 c1b = *(const float4*)(xr + p0 + 4);
    int br = p0 + 8;
    float4 c2 = *(const float4*)(xr + (br > W-4 ? W-4 : br));
    float wq[12];                  // wq[m] = x[p0-2+m] (zero padded)
    wq[0] = (lane > 0) ? c0.z : 0.f;
    wq[1] = (lane > 0) ? c0.w : 0.f;
    wq[2] = c1.x; wq[3] = c1.y; wq[4] = c1.z; wq[5] = c1.w;
    wq[6] = c1b.x; wq[7] = c1b.y; wq[8] = c1b.z; wq[9] = c1b.w;
    wq[10] = (lane < 31) ? c2.x : 0.f;
    wq[11] = (lane < 31) ? c2.y : 0.f;

    float s1[8];
    #pragma unroll
    for (int k = 0; k < 8; k++) {
        float s = 0.f;
        #pragma unroll
        for (int i = 0; i < 5; i++) s = fmaf(w1[i], wq[k + i], s);
        s1[k] = s;
    }

    float wf[26];
    {
        float vv = __shfl_up_sync(0xffffffffu, s1[7], 2);
        wf[0] = (lane >= 2) ? vv : 0.f;
    }
    #pragma unroll
    for (int k = 0; k < 8; k++) {
        float vv = __shfl_up_sync(0xffffffffu, s1[k], 1);
        wf[1 + k] = (lane >= 1) ? vv : 0.f;
    }
    #pragma unroll
    for (int k = 0; k < 8; k++) wf[9 + k] = s1[k];
    #pragma unroll
    for (int k = 0; k < 8; k++) {
        float vv = __shfl_down_sync(0xffffffffu, s1[k], 1);
        wf[17 + k] = (lane <= 30) ? vv : 0.f;
    }
    {
        float vv = __shfl_down_sync(0xffffffffu, s1[0], 2);
        wf[25] = (lane <= 29) ? vv : 0.f;
    }

    __nv_bfloat16 ob[8];
    float thread_sum = 0.f;
    #pragma unroll
    for (int d = 0; d < 8; d++) {
        float a = 0.f;
        #pragma unroll
        for (int j = 0; j < 7; j++) a = fmaf(w2[j], wf[d + 3*j], a);
        thread_sum += a;
        ob[d] = __float2bfloat16(a);
    }
    *(uint4*)(g_h + (size_t)bc*HW + (size_t)row*W + p0) = *(uint4*)ob;

    float s = thread_sum;
    #pragma unroll
    for (int off = 16; off; off >>= 1) s += __shfl_down_sync(0xffffffffu, s, off);
    if ((t & 31) == 0) ssum[t >> 5] = s;
    __syncthreads();
    if (t == 0) {
        float tot = 0.f;
        #pragma unroll
        for (int i = 0; i < 8; i++) tot += ssum[i];
        g_hpart[bc*32 + rowblk] = tot;
    }
}

// ---------------- K1v: vertical two-stage conv (64x128 tile, 32 rows/thread) --------
__global__ void __launch_bounds__(256) k1_v(const float* __restrict__ x,
                                            const float* __restrict__ v1w,
                                            const float* __restrict__ v2w) {
    int blk2 = blockIdx.x;
    int t = threadIdx.x;
    __shared__ float ssum[8];

    int xt = blk2 & 1;
    int yt = (blk2 >> 1) & 3;
    int bc = blk2 >> 3;
    int c = bc & (C - 1);
    int tx = t & 127, ty = t >> 7;
    int col = xt*128 + tx;
    int y0 = yt*64 + ty*32;
    const float* xc = x + (size_t)bc*HW + col;

    float w1[5], w2[7];
    #pragma unroll
    for (int i = 0; i < 5; i++) w1[i] = v1w[c*5 + i];
    #pragma unroll
    for (int j = 0; j < 7; j++) w2[j] = v2w[c*7 + j];

    float acc[32];
    #pragma unroll
    for (int d = 0; d < 32; d++) acc[d] = 0.f;

    float xr[5];
    #pragma unroll
    for (int m = 0; m < 4; m++) {
        int gy = y0 - 11 + m;
        xr[m] = (gy >= 0 && gy < H) ? xc[gy*W] : 0.f;
    }
    #pragma unroll
    for (int k = 0; k < 50; k++) {
        int gy = y0 - 7 + k;
        xr[(k + 4) % 5] = (gy >= 0 && gy < H) ? xc[gy*W] : 0.f;
        float s = 0.f;
        #pragma unroll
        for (int i = 0; i < 5; i++) s = fmaf(w1[i], xr[(k + i) % 5], s);
        int gy1 = y0 - 9 + k;
        s = (gy1 >= 0 && gy1 < H) ? s : 0.f;
        #pragma unroll
        for (int j = 0; j < 7; j++) {
            int d = k - 3*j;
            if (d >= 0 && d < 32) acc[d] = fmaf(w2[j], s, acc[d]);
        }
    }
    __nv_bfloat16* vpb = g_v + (size_t)bc*HW + col;
    float thread_sum = 0.f;
    #pragma unroll
    for (int d = 0; d < 32; d++) {
        vpb[(y0 + d)*W] = __float2bfloat16(acc[d]);
        thread_sum += acc[d];
    }

    float s = thread_sum;
    #pragma unroll
    for (int off = 16; off; off >>= 1) s += __shfl_down_sync(0xffffffffu, s, off);
    if ((t & 31) == 0) ssum[t >> 5] = s;
    __syncthreads();
    if (t == 0) {
        float tot = 0.f;
        #pragma unroll
        for (int i = 0; i < 8; i++) tot += ssum[i];
        g_vpart[bc*32 + (yt*2 + xt)] = tot;
    }
}

// ---------------- K2: gate MLP + softmax + fw->bf16 conversion -----------------------
__global__ void __launch_bounds__(512) k2_gate(const float* __restrict__ g1,
                                               const float* __restrict__ g2,
                                               const float* __restrict__ g2b,
                                               const float* __restrict__ fw) {
    __shared__ float shs[BB*C];
    __shared__ float svs[BB*C];
    __shared__ float sp[BB][32][4];
    __shared__ float sg[BB][32];
    __shared__ float sl[BB][2];
    int t = threadIdx.x;

    for (int i = t; i < C*C; i += 512) g_fwb[i] = __float2bfloat16(fw[i]);

    {
        int bc = t;
        float s = 0.f;
        #pragma unroll 8
        for (int i = 0; i < 32; i++) s += g_hpart[bc*32 + i];
        shs[bc] = s;
        s = 0.f;
        #pragma unroll
        for (int i = 0; i < 8; i++) s += g_vpart[bc*32 + i];
        svs[bc] = s;
    }
    __syncthreads();
    {
        int b = t >> 7, k = (t >> 2) & 31, c4 = t & 3;
        const float inv = 1.f / 65536.f;
        float acc = 0.f;
        int cc0 = c4 * 64;
        #pragma unroll 8
        for (int cc = cc0; cc < cc0 + 64; cc++) {
            float p = (cc < C ? shs[b*C + cc] : svs[b*C + cc - C]) * inv;
            acc = fmaf(p, g1[k*(2*C) + cc], acc);
        }
        sp[b][k][c4] = acc;
    }
    __syncthreads();
    if (t < BB*32) {
        int b = t >> 5, k = t & 31;
        float g = sp[b][k][0] + sp[b][k][1] + sp[b][k][2] + sp[b][k][3];
        float sig = 1.f / (1.f + expf(-g));
        sg[b][k] = g * sig;
    }
    __syncthreads();
    if (t < BB*2) {
        int b = t >> 1, j = t & 1;
        float acc = g2b[j];
        #pragma unroll
        for (int k = 0; k < 32; k++) acc = fmaf(sg[b][k], g2[j*32 + k], acc);
        sl[b][j] = acc;
    }
    __syncthreads();
    if (t < BB) {
        float a = sl[t][0], b2 = sl[t][1];
        float m = fmaxf(a, b2);
        float e0 = expf(a - m), e1 = expf(b2 - m);
        float inv = 1.f / (e0 + e1);
        g_gate[t*2 + 0] = e0 * inv;
        g_gate[t*2 + 1] = e1 * inv;
    }
}

// ---------------- K3: persistent split-GEMM, x+h+v all through cp.async pipeline -----
#define SFW_STRIDE 136                   // bf16 elems per row (272B)
#define SB_STRIDE  72                    // bf16 elems per row (144B)
#define SB_BYTES   (128*SB_STRIDE*2)     // 18432
#define SX_STRIDE  72                    // floats per row (288B)
#define SX_BYTES   (128*SX_STRIDE*4)     // 36864
#define STAGE_BYTES (2*SB_BYTES + SX_BYTES)  // 73728: H + V + X
#define K3_SMEM    (2*STAGE_BYTES)       // 147456
#define NB3 152
#define NTILES (BB*(HW/64))              // 4096

__device__ __forceinline__ void cpa16(unsigned dst, const void* src) {
    asm volatile("cp.async.cg.shared.global [%0], [%1], 16;" :: "r"(dst), "l"(src));
}
__device__ __forceinline__ void ldsm_x4(unsigned addr, unsigned &r0, unsigned &r1,
                                        unsigned &r2, unsigned &r3) {
    asm volatile("ldmatrix.sync.aligned.m8n8.x4.shared.b16 {%0,%1,%2,%3}, [%4];"
                 : "=r"(r0), "=r"(r1), "=r"(r2), "=r"(r3) : "r"(addr));
}
__device__ __forceinline__ void ldsm_x4t(unsigned addr, unsigned &r0, unsigned &r1,
                                         unsigned &r2, unsigned &r3) {
    asm volatile("ldmatrix.sync.aligned.m8n8.x4.trans.shared.b16 {%0,%1,%2,%3}, [%4];"
                 : "=r"(r0), "=r"(r1), "=r"(r2), "=r"(r3) : "r"(addr));
}
__device__ __forceinline__ void mma16816(float* d, const unsigned* a,
                                         unsigned b0, unsigned b1) {
    asm volatile("mma.sync.aligned.m16n8k16.row.col.f32.bf16.bf16.f32 "
                 "{%0,%1,%2,%3}, {%4,%5,%6,%7}, {%8,%9}, {%0,%1,%2,%3};"
                 : "+f"(d[0]), "+f"(d[1]), "+f"(d[2]), "+f"(d[3])
                 : "r"(a[0]), "r"(a[1]), "r"(a[2]), "r"(a[3]), "r"(b0), "r"(b1));
}

__device__ __forceinline__ void k3_stage(unsigned su, int tile, int t,
                                         const float* __restrict__ x) {
    int b = tile >> 10;
    int p0 = (tile & 1023) * 64;
    // h, v: 128 c-rows x 8 chunks of 16B
    #pragma unroll
    for (int rep = 0; rep < 4; rep++) {
        int idx = t + rep*256;
        int cc = idx >> 3, q = idx & 7;
        size_t gi = ((size_t)(b*C + cc))*HW + p0 + q*8;
        unsigned doff = cc*(SB_STRIDE*2) + q*16;
        cpa16(su + doff, g_h + gi);
        cpa16(su + SB_BYTES + doff, g_v + gi);
    }
    // x: 128 c-rows x 16 chunks of 16B
    #pragma unroll
    for (int rep = 0; rep < 8; rep++) {
        int idx = t + rep*256;
        int cc = idx >> 4, q = idx & 15;
        size_t gi = ((size_t)(b*C + cc))*HW + p0 + q*4;
        cpa16(su + 2*SB_BYTES + cc*(SX_STRIDE*4) + q*16, x + gi);
    }
}

__global__ void __launch_bounds__(256, 1) k3_fuse(const float* __restrict__ x,
                                                  const float* __restrict__ fb,
                                                  float* __restrict__ out) {
    extern __shared__ __align__(16) char sm3[];
    unsigned st0u = (unsigned)__cvta_generic_to_shared(sm3);
    unsigned st1u = st0u + STAGE_BYTES;
    int t = threadIdx.x;
    int w = t >> 5, l = t & 31;

    int aRow = 16*w + (l & 15);
    int aColHalf = (l >> 4) * 8;
    int bRowLocal = (l & 7) + (((l >> 3) & 1) << 3);
    int bColHalf = (l >> 4) * 8;
    int r0 = 16*w + (l >> 2);

    // ---- prologue: stage fw into buf0, hoist A fragments to registers ----
    #pragma unroll
    for (int rep = 0; rep < 8; rep++) {
        int idx = t + rep*256;
        int row = idx >> 4, cq = idx & 15;
        cpa16(st0u + row*(SFW_STRIDE*2) + cq*16, g_fwb + row*128 + cq*8);
    }
    asm volatile("cp.async.commit_group;");
    asm volatile("cp.async.wait_group 0;");
    __syncthreads();
    unsigned afr[8][4];
    #pragma unroll
    for (int kk = 0; kk < 8; kk++) {
        unsigned aAddr = st0u + (unsigned)(aRow*SFW_STRIDE + kk*16 + aColHalf)*2u;
        ldsm_x4(aAddr, afr[kk][0], afr[kk][1], afr[kk][2], afr[kk][3]);
    }
    __syncthreads();   // all warps done with fw region before overwrite

    int tile = blockIdx.x;
    if (tile < NTILES) k3_stage(st0u, tile, t, x);
    asm volatile("cp.async.commit_group;");
    if (tile + NB3 < NTILES) k3_stage(st1u, tile + NB3, t, x);
    asm volatile("cp.async.commit_group;");

    float fb0 = fb[r0], fb1 = fb[r0 + 8];

    for (int it = 0; tile < NTILES; tile += NB3, it++) {
        unsigned cur = (it & 1) ? st1u : st0u;
        asm volatile("cp.async.wait_group 1;");
        __syncthreads();

        int b = tile >> 10;
        int p0 = (tile & 1023) * 64;
        float wh = g_gate[b*2 + 0], wv = g_gate[b*2 + 1];
        unsigned sHu = cur, sVu = cur + SB_BYTES;
        const char* sX = sm3 + (cur - st0u) + 2*SB_BYTES;

        float accH[8][4], accV[8][4];
        #pragma unroll
        for (int n = 0; n < 8; n++)
            #pragma unroll
            for (int i = 0; i < 4; i++) { accH[n][i] = 0.f; accV[n][i] = 0.f; }

        #pragma unroll
        for (int kk = 0; kk < 8; kk++) {
            #pragma unroll
            for (int nn = 0; nn < 4; nn++) {
                unsigned boff = (unsigned)((kk*16 + bRowLocal)*SB_STRIDE
                                           + nn*16 + bColHalf)*2u;
                unsigned b0, b1, b2, b3;
                ldsm_x4t(sHu + boff, b0, b1, b2, b3);
                mma16816(accH[2*nn],     afr[kk], b0, b1);
                mma16816(accH[2*nn + 1], afr[kk], b2, b3);
                ldsm_x4t(sVu + boff, b0, b1, b2, b3);
                mma16816(accV[2*nn],     afr[kk], b0, b1);
                mma16816(accV[2*nn + 1], afr[kk], b2, b3);
            }
        }

        int pxl = 2*(l & 3);
        #pragma unroll
        for (int nt = 0; nt < 8; nt++) {
            int px = pxl + nt*8;
            float2 xv0 = *(const float2*)(sX + r0*(SX_STRIDE*4) + px*4);
            float a0 = fmaf(wh, accH[nt][0], wv * accV[nt][0]);
            float a1 = fmaf(wh, accH[nt][1], wv * accV[nt][1]);
            float2 o0;
            o0.x = xv0.x * (0.5f + 0.5f*(a0 + fb0));
            o0.y = xv0.y * (0.5f + 0.5f*(a1 + fb0));
            size_t base0 = ((size_t)(b*C + r0))*HW + p0 + px;
            *(float2*)(out + base0) = o0;
            float2 xv1 = *(const float2*)(sX + (r0 + 8)*(SX_STRIDE*4) + px*4);
            float a2 = fmaf(wh, accH[nt][2], wv * accV[nt][2]);
            float a3 = fmaf(wh, accH[nt][3], wv * accV[nt][3]);
            float2 o1;
            o1.x = xv1.x * (0.5f + 0.5f*(a2 + fb1));
            o1.y = xv1.y * (0.5f + 0.5f*(a3 + fb1));
            *(float2*)(out + base0 + (size_t)8*HW) = o1;
        }
        __syncthreads();

        int stile = tile + 2*NB3;
        if (stile < NTILES) k3_stage(cur, stile, t, x);
        asm volatile("cp.async.commit_group;");
    }
}

// ---------------- launch -------------------------------------------------------------
extern "C" void kernel_launch(void* const* d_in, const int* in_sizes, int n_in,
                              void* d_out, int out_size) {
    const float* x   = (const float*)d_in[0];
    const float* h1  = (const float*)d_in[1];
    const float* h2  = (const float*)d_in[2];
    const float* v1  = (const float*)d_in[3];
    const float* v2  = (const float*)d_in[4];
    const float* g1  = (const float*)d_in[5];
    const float* g2  = (const float*)d_in[6];
    const float* g2b = (const float*)d_in[7];
    const float* fw  = (const float*)d_in[8];
    const float* fb  = (const float*)d_in[9];
    float* out = (float*)d_out;

    static int smem_set = 0;
    if (!smem_set) {
        cudaFuncSetAttribute(k3_fuse, cudaFuncAttributeMaxDynamicSharedMemorySize,
                             K3_SMEM);
        smem_set = 1;
    }

    k1_h<<<GRID_H, 256>>>(x, h1, h2);
    k1_v<<<GRID_V, 256>>>(x, v1, v2);
    k2_gate<<<1, 512>>>(g1, g2, g2b, fw);
    k3_fuse<<<NB3, 256, K3_SMEM>>>(x, fb, out);
}